// round 4
// baseline (speedup 1.0000x reference)
#include <cuda_runtime.h>
#include <cstdint>

#define NB 32
#define E  512
#define IND 128
#define OUTD 64
#define NT 3
#define QD 128
#define CD 128   // 2*OUTD

// ---------------- scratch (__device__ globals: no allocs allowed) ----------
__device__ float g_wsrc[NT*NB*IND];
__device__ float g_wdst[NT*NB*IND];
__device__ float g_ssrc[NT*NB*E];
__device__ float g_sdst[NT*NB*E];
__device__ float g_hm[(size_t)NB*E*OUTD];
__device__ float g_rmax[NB*E];
__device__ float g_rinvZ[NB*E];
__device__ float g_part[(size_t)3*NB*E*OUTD];   // split-K partials (kz=1..3)

// ---------------- fast exp on FMA/ALU pipes (no MUFU) -----------------------
// exp(s) for s <= ~0; underflows cleanly to 0 for s <= -88. ~2e-6 rel err.
__device__ __forceinline__ float fexp(float s) {
    float x = fmaxf(s * 1.4426950408889634f, -127.f);
    float r  = __fadd_rn(x, 12582912.f);            // round-to-nearest int
    float nf = __fadd_rn(r, -12582912.f);
    float f  = x - nf;                              // f in [-0.5, 0.5]
    int   n  = __float_as_int(r);                   // 0x4B400000 + k
    float sc = __int_as_float((n + (127 - 0x4B400000)) << 23);  // 2^k
    float p = 1.3333558e-3f;
    p = fmaf(p, f, 9.6181291e-3f);
    p = fmaf(p, f, 5.5504109e-2f);
    p = fmaf(p, f, 2.4022651e-1f);
    p = fmaf(p, f, 6.9314718e-1f);
    p = fmaf(p, f, 1.0f);
    return p * sc;
}

// packed fp32x2 FMA (sm_100+ base PTX; 2x FFMA rate)
#define FMA2(acc, a, b) \
    asm("fma.rn.f32x2 %0, %1, %2, %0;" : "+l"(acc) : "l"(a), "l"(b))

// ---------------------------------------------------------------------------
// Kernel 1: per (t,n) fold qg*a into 128-vectors w_src/w_dst
// ---------------------------------------------------------------------------
__global__ void prep_kernel(const float* __restrict__ qv,
                            const float* __restrict__ Wt,
                            const float* __restrict__ at,
                            const float* __restrict__ W1,
                            const float* __restrict__ W2) {
    int t = blockIdx.x / NB, n = blockIdx.x % NB;
    int c = threadIdx.x;                       // 0..127
    __shared__ float sq[QD], sg1[CD], su[CD];

    sq[c] = qv[n*QD + c];
    __syncthreads();

    const float* w1 = W1 + t*QD*CD;
    float acc = 0.f;
    #pragma unroll 8
    for (int q = 0; q < QD; q++) acc += sq[q] * w1[q*CD + c];
    sg1[c] = fmaxf(acc, 0.f);
    __syncthreads();

    const float* w2 = W2 + t*CD*CD;
    acc = 0.f;
    #pragma unroll 8
    for (int q = 0; q < CD; q++) acc += sg1[q] * w2[q*CD + c];
    float qg = 1.f / (1.f + expf(-acc));
    su[c] = qg * at[t*CD + c];
    __syncthreads();

    const float* W = Wt + (t*IND + c)*OUTD;
    float ws = 0.f, wd = 0.f;
    #pragma unroll 8
    for (int o = 0; o < OUTD; o++) {
        float w = W[o];
        ws += w * su[o];
        wd += w * su[OUTD + o];
    }
    g_wsrc[(t*NB + n)*IND + c] = ws;
    g_wdst[(t*NB + n)*IND + c] = wd;
}

// ---------------------------------------------------------------------------
// Kernel 2 (fused): h_m = (x @ W_type[2]) * mask  AND  s_src/s_dst dots
// ---------------------------------------------------------------------------
__global__ void hm_ssd_kernel(const float* __restrict__ x,
                              const float* __restrict__ Wt,
                              const float* __restrict__ mask) {
    __shared__ float Ws[IND][OUTD + 4];
    __shared__ float Xs[64][IND + 4];
    __shared__ float sw[6][IND];
    int n = blockIdx.x, e0 = blockIdx.y * 64;
    int tid = threadIdx.x;                     // 256

    const float4* Wg = (const float4*)(Wt + 2*IND*OUTD);
    for (int k = tid; k < IND*OUTD/4; k += 256) {
        float4 v = Wg[k];
        int row = (k*4) / OUTD, col = (k*4) % OUTD;
        *(float4*)&Ws[row][col] = v;
    }
    const float4* Xg = (const float4*)(x + ((size_t)n*E + e0)*IND);
    for (int k = tid; k < 64*IND/4; k += 256) {
        float4 v = Xg[k];
        int row = (k*4) / IND, col = (k*4) % IND;
        *(float4*)&Xs[row][col] = v;
    }
    for (int k = tid; k < 6*IND; k += 256) {
        int v = k / IND, i = k % IND;
        int t = v % 3;
        sw[v][i] = (v < 3) ? g_wsrc[(t*NB+n)*IND + i] : g_wdst[(t*NB+n)*IND + i];
    }
    __syncthreads();

    // ---- ssd part ----
    {
        int r = tid >> 2, q = tid & 3;
        float a[6] = {0.f,0.f,0.f,0.f,0.f,0.f};
        #pragma unroll 8
        for (int kk = 0; kk < 32; kk++) {
            int k = q + 4*kk;
            float xv = Xs[r][k];
            a[0] += xv * sw[0][k]; a[1] += xv * sw[1][k]; a[2] += xv * sw[2][k];
            a[3] += xv * sw[3][k]; a[4] += xv * sw[4][k]; a[5] += xv * sw[5][k];
        }
        #pragma unroll
        for (int off = 1; off <= 2; off <<= 1)
            #pragma unroll
            for (int u = 0; u < 6; u++)
                a[u] += __shfl_xor_sync(0xffffffffu, a[u], off);
        if (q == 0) {
            int e = e0 + r;
            #pragma unroll
            for (int t = 0; t < 3; t++) {
                g_ssrc[(t*NB+n)*E + e] = a[t];
                g_sdst[(t*NB+n)*E + e] = a[t+3];
            }
        }
    }

    // ---- GEMM 4x4 ----
    int dq = tid & 15, eq = tid >> 4;
    int d0 = dq*4, el = eq*4;
    float acc[4][4] = {};
    #pragma unroll 8
    for (int k = 0; k < IND; k++) {
        float4 b = *(const float4*)&Ws[k][d0];
        float a0 = Xs[el+0][k], a1 = Xs[el+1][k], a2 = Xs[el+2][k], a3 = Xs[el+3][k];
        acc[0][0]+=a0*b.x; acc[0][1]+=a0*b.y; acc[0][2]+=a0*b.z; acc[0][3]+=a0*b.w;
        acc[1][0]+=a1*b.x; acc[1][1]+=a1*b.y; acc[1][2]+=a1*b.z; acc[1][3]+=a1*b.w;
        acc[2][0]+=a2*b.x; acc[2][1]+=a2*b.y; acc[2][2]+=a2*b.z; acc[2][3]+=a2*b.w;
        acc[3][0]+=a3*b.x; acc[3][1]+=a3*b.y; acc[3][2]+=a3*b.z; acc[3][3]+=a3*b.w;
    }
    #pragma unroll
    for (int r = 0; r < 4; r++) {
        float mk = mask[n*E + e0 + el + r];
        float4 o = make_float4(acc[r][0]*mk, acc[r][1]*mk, acc[r][2]*mk, acc[r][3]*mk);
        *(float4*)&g_hm[((size_t)n*E + e0 + el + r)*OUTD + d0] = o;
    }
}

// ---------------------------------------------------------------------------
// Kernel 3: row softmax stats, one warp per row, fexp (no MUFU)
// ---------------------------------------------------------------------------
__global__ void rowstats_kernel(const int* __restrict__ adj) {
    int base = blockIdx.x * 16;
    int n = base / E;
    __shared__ float sds[3][E];
    int tid = threadIdx.x;
    #pragma unroll
    for (int k = tid; k < 3*E; k += 512)
        sds[k >> 9][k & 511] = g_sdst[((k >> 9)*NB + n)*E + (k & 511)];
    __syncthreads();

    int warp = tid >> 5, lane = tid & 31;
    int row = base + warp;
    int i = row & (E-1);
    float sr0 = g_ssrc[(0*NB+n)*E + i];
    float sr1 = g_ssrc[(1*NB+n)*E + i];
    float sr2 = g_ssrc[(2*NB+n)*E + i];
    const int* arow = adj + (size_t)row * E;

    float sc[16];
    #pragma unroll
    for (int k = 0; k < 16; k++) {
        int j = lane + 32*k;
        int v = arow[j];
        float s = -1e30f;
        if (v > 0) {
            float srr = (v == 1) ? sr0 : ((v == 2) ? sr1 : sr2);
            float t2 = srr + sds[v-1][j];
            s = (t2 >= 0.f) ? t2 : 0.2f*t2;
        }
        sc[k] = s;
    }
    float m = sc[0];
    #pragma unroll
    for (int k = 1; k < 16; k++) m = fmaxf(m, sc[k]);
    #pragma unroll
    for (int off = 16; off > 0; off >>= 1) m = fmaxf(m, __shfl_xor_sync(~0u, m, off));
    float sum = 0.f;
    #pragma unroll
    for (int k = 0; k < 16; k++) sum += fexp(sc[k] - m);
    #pragma unroll
    for (int off = 16; off > 0; off >>= 1) sum += __shfl_xor_sync(~0u, sum, off);
    if (lane == 0) { g_rmax[row] = m; g_rinvZ[row] = 1.f / sum; }
}

// ---------------------------------------------------------------------------
// Kernel 4: split-K output GEMM, coefs on the fly (fexp), packed f32x2 FMA.
// grid (NB, E/64, 4): kz selects i-range [kz*128, kz*128+128).
// kz=0 -> out, kz>0 -> g_part slice. Dynamic smem (52 KB): Cs | Hdup | stats.
// Hdup duplicates each H value into a (v,v) pair so the FFMA2 d-broadcast
// comes from one LDS.64, no register packing MOVs.
// ---------------------------------------------------------------------------
__global__ void __launch_bounds__(256)
out_kernel(const int* __restrict__ adj, float* __restrict__ out) {
    extern __shared__ float smp[];
    float (*Cs)[68]    = (float(*)[68])smp;                 // 64 x 68
    float (*Hdup)[132] = (float(*)[132])(smp + 4352);       // 64 x 132 (dup pairs)
    float* sds = smp + 4352 + 8448;                          // [3][64]
    float* ssr = sds + 192;                                  // [3][64]
    float* smx = ssr + 192;                                  // [64]
    float* siz = smx + 64;                                   // [64]

    const int n = blockIdx.x, j0t = blockIdx.y * 64, kz = blockIdx.z;
    const int tid = threadIdx.x;               // 256
    const int jq = tid & 15, dq = tid >> 4;    // j block 4*jq, d block 4*dq

    if (tid < 192) sds[tid] = g_sdst[((tid >> 6)*NB + n)*E + j0t + (tid & 63)];

    unsigned long long acc2[2][4] = {};        // [j-pair][d]

    for (int cc = 0; cc < 2; cc++) {
        const int ic = kz*128 + cc*64;
        __syncthreads();
        if (tid < 64)       { smx[tid] = g_rmax[n*E + ic + tid]; siz[tid] = g_rinvZ[n*E + ic + tid]; }
        else if (tid < 256) { int t = (tid-64)/64, i = (tid-64)%64;
                              ssr[t*64 + i] = g_ssrc[(t*NB + n)*E + ic + i]; }
        const float4* Hg = (const float4*)(g_hm + ((size_t)n*E + ic)*OUTD);
        for (int k = tid; k < 64*OUTD/4; k += 256) {
            float4 v = Hg[k];
            int row = (k*4) / OUTD, col = (k*4) % OUTD;
            *(float4*)&Hdup[row][2*col]     = make_float4(v.x, v.x, v.y, v.y);
            *(float4*)&Hdup[row][2*col + 4] = make_float4(v.z, v.z, v.w, v.w);
        }
        __syncthreads();

        // coef tile: thread handles 4 i-rows x 4 j
        const int* abase = adj + ((size_t)n*E + ic)*E + j0t;
        #pragma unroll
        for (int r = 0; r < 4; r++) {
            int il = dq*4 + r;
            const int4 a4 = *(const int4*)(abase + (size_t)il*E + jq*4);
            float m = smx[il], z = siz[il];
            float s0 = ssr[il], s1 = ssr[64 + il], s2 = ssr[128 + il];
            int vv[4] = {a4.x, a4.y, a4.z, a4.w};
            float c[4];
            #pragma unroll
            for (int q = 0; q < 4; q++) {
                int v = vv[q];
                float score = -1e30f;
                if (v > 0) {
                    float srr = (v == 1) ? s0 : ((v == 2) ? s1 : s2);
                    float t2 = srr + sds[(v-1)*64 + jq*4 + q];
                    score = (t2 >= 0.f) ? t2 : 0.2f*t2;
                }
                c[q] = fexp(score - m) * z;
            }
            *(float4*)&Cs[il][jq*4] = make_float4(c[0], c[1], c[2], c[3]);
        }
        __syncthreads();

        #pragma unroll 16
        for (int k = 0; k < 64; k++) {
            ulonglong2 c01 = *(const ulonglong2*)&Cs[k][jq*4];     // (j0,j1),(j2,j3)
            ulonglong2 b01 = *(const ulonglong2*)&Hdup[k][dq*8];   // (d0,d0),(d1,d1)
            ulonglong2 b23 = *(const ulonglong2*)&Hdup[k][dq*8+4]; // (d2,d2),(d3,d3)
            FMA2(acc2[0][0], c01.x, b01.x); FMA2(acc2[0][1], c01.x, b01.y);
            FMA2(acc2[0][2], c01.x, b23.x); FMA2(acc2[0][3], c01.x, b23.y);
            FMA2(acc2[1][0], c01.y, b01.x); FMA2(acc2[1][1], c01.y, b01.y);
            FMA2(acc2[1][2], c01.y, b23.x); FMA2(acc2[1][3], c01.y, b23.y);
        }
    }

    float* dst = (kz == 0) ? out : (g_part + (size_t)(kz-1)*NB*E*OUTD);
    #pragma unroll
    for (int jp = 0; jp < 2; jp++) {
        uint2 u0 = *(uint2*)&acc2[jp][0];
        uint2 u1 = *(uint2*)&acc2[jp][1];
        uint2 u2 = *(uint2*)&acc2[jp][2];
        uint2 u3 = *(uint2*)&acc2[jp][3];
        int jrow = j0t + jq*4 + jp*2;
        *(float4*)&dst[((size_t)n*E + jrow)*OUTD + dq*4] =
            make_float4(__uint_as_float(u0.x), __uint_as_float(u1.x),
                        __uint_as_float(u2.x), __uint_as_float(u3.x));
        *(float4*)&dst[((size_t)n*E + jrow + 1)*OUTD + dq*4] =
            make_float4(__uint_as_float(u0.y), __uint_as_float(u1.y),
                        __uint_as_float(u2.y), __uint_as_float(u3.y));
    }
}

// ---------------------------------------------------------------------------
// Kernel 5: out += sum of 3 partial slices
// ---------------------------------------------------------------------------
__global__ void combine_kernel(float* __restrict__ out) {
    const size_t S4 = (size_t)NB*E*OUTD/4;     // float4 stride
    size_t idx = (size_t)blockIdx.x*256 + threadIdx.x;
    float4 a  = ((const float4*)out)[idx];
    float4 p0 = ((const float4*)g_part)[idx];
    float4 p1 = ((const float4*)g_part)[idx + S4];
    float4 p2 = ((const float4*)g_part)[idx + 2*S4];
    a.x += p0.x + p1.x + p2.x;
    a.y += p0.y + p1.y + p2.y;
    a.z += p0.z + p1.z + p2.z;
    a.w += p0.w + p1.w + p2.w;
    ((float4*)out)[idx] = a;
}

// ---------------------------------------------------------------------------
extern "C" void kernel_launch(void* const* d_in, const int* in_sizes, int n_in,
                              void* d_out, int out_size) {
    const float* x    = (const float*)d_in[0];   // input_state (32,512,128)
    const int*   adj  = (const int*)  d_in[1];   // adj (32,512,512)
    const float* qv   = (const float*)d_in[2];   // query_vec (32,128)
    const float* mask = (const float*)d_in[3];   // node_mask (32,512,1)
    const float* Wt   = (const float*)d_in[4];   // W_type (3,128,64)
    const float* at   = (const float*)d_in[5];   // a_type (3,128,1)
    const float* W1   = (const float*)d_in[6];   // qattn_W1 (3,128,128)
    const float* W2   = (const float*)d_in[7];   // qattn_W2 (3,128,128)
    float* out = (float*)d_out;                  // (32,512,64)

    const int OUT_SMEM = (4352 + 8448 + 192 + 192 + 64 + 64) * 4;  // 53248 B
    cudaFuncSetAttribute(out_kernel, cudaFuncAttributeMaxDynamicSharedMemorySize,
                         OUT_SMEM);

    prep_kernel<<<NT*NB, 128>>>(qv, Wt, at, W1, W2);
    hm_ssd_kernel<<<dim3(NB, E/64), 256>>>(x, Wt, mask);
    rowstats_kernel<<<NB*E/16, 512>>>(adj);
    out_kernel<<<dim3(NB, E/64, 4), 256, OUT_SMEM>>>(adj, out);
    combine_kernel<<<NB*E*OUTD/4/256, 256>>>(out);
}